// round 17
// baseline (speedup 1.0000x reference)
#include <cuda_runtime.h>
#include <cuda_bf16.h>
#include <stdint.h>

#define Bq 4
#define Sq 2048
#define Eq 1024
#define Hq 16

#define SW128(o) ((o) ^ (((o) >> 3) & 0x70))
#define SW256(o) ((o) ^ (((o) >> 4) & 0x70))

// ---------------- scratch ----------------
__device__ __nv_bfloat16 g_Qh[(size_t)Bq*Hq*Sq*64];
__device__ __nv_bfloat16 g_Ql[(size_t)Bq*Hq*Sq*64];
__device__ __nv_bfloat16 g_Kh[(size_t)Bq*Hq*Sq*64];
__device__ __nv_bfloat16 g_Kl[(size_t)Bq*Hq*Sq*64];
__device__ __nv_bfloat16 g_Vh[(size_t)Bq*Hq*Sq*64];
__device__ __nv_bfloat16 g_Vl[(size_t)Bq*Hq*Sq*64];
__device__ float g_ctx[(size_t)Bq*Sq*Eq];
__device__ float g_proj[(size_t)Bq*Sq*Eq];
__device__ float g_rowmax[Bq*Hq*Sq];
__device__ float g_rinv[Bq*Hq*Sq];
__device__ float2 g_pstat[(size_t)Bq*Hq*Sq*64];

// ---------------- helpers ----------------
__device__ __forceinline__ void ldsm4(uint32_t& r0, uint32_t& r1, uint32_t& r2, uint32_t& r3, uint32_t a) {
    asm volatile("ldmatrix.sync.aligned.m8n8.x4.shared.b16 {%0,%1,%2,%3},[%4];"
                 : "=r"(r0), "=r"(r1), "=r"(r2), "=r"(r3) : "r"(a));
}
__device__ __forceinline__ void ldsm4t(uint32_t& r0, uint32_t& r1, uint32_t& r2, uint32_t& r3, uint32_t a) {
    asm volatile("ldmatrix.sync.aligned.m8n8.x4.trans.shared.b16 {%0,%1,%2,%3},[%4];"
                 : "=r"(r0), "=r"(r1), "=r"(r2), "=r"(r3) : "r"(a));
}
__device__ __forceinline__ void mmab(float* c, const uint32_t* a, const uint32_t* b) {
    asm volatile("mma.sync.aligned.m16n8k16.row.col.f32.bf16.bf16.f32 "
                 "{%0,%1,%2,%3},{%4,%5,%6,%7},{%8,%9},{%0,%1,%2,%3};"
                 : "+f"(c[0]), "+f"(c[1]), "+f"(c[2]), "+f"(c[3])
                 : "r"(a[0]), "r"(a[1]), "r"(a[2]), "r"(a[3]), "r"(b[0]), "r"(b[1]));
}
__device__ __forceinline__ uint32_t smaddr(const void* p) {
    return (uint32_t)__cvta_generic_to_shared(p);
}
__device__ __forceinline__ void split4(float4 v, uint2& h, uint2& l) {
    __nv_bfloat16 h0 = __float2bfloat16(v.x), h1 = __float2bfloat16(v.y);
    __nv_bfloat16 h2 = __float2bfloat16(v.z), h3 = __float2bfloat16(v.w);
    __nv_bfloat16 l0 = __float2bfloat16(v.x - __bfloat162float(h0));
    __nv_bfloat16 l1 = __float2bfloat16(v.y - __bfloat162float(h1));
    __nv_bfloat16 l2 = __float2bfloat16(v.z - __bfloat162float(h2));
    __nv_bfloat16 l3 = __float2bfloat16(v.w - __bfloat162float(h3));
    __nv_bfloat162 ph0(h0, h1), ph1(h2, h3), pl0(l0, l1), pl1(l2, l3);
    h.x = *(uint32_t*)&ph0; h.y = *(uint32_t*)&ph1;
    l.x = *(uint32_t*)&pl0; l.y = *(uint32_t*)&pl1;
}
__device__ __forceinline__ void pk2bf(float a, float b, uint32_t& h, uint32_t& l) {
    __nv_bfloat16 ha = __float2bfloat16(a), hb = __float2bfloat16(b);
    __nv_bfloat16 la = __float2bfloat16(a - __bfloat162float(ha));
    __nv_bfloat16 lb = __float2bfloat16(b - __bfloat162float(hb));
    __nv_bfloat162 ph(ha, hb), pl(la, lb);
    h = *(uint32_t*)&ph; l = *(uint32_t*)&pl;
}
__device__ __forceinline__ void cpasync16(uint32_t dst, const void* src) {
    asm volatile("cp.async.ca.shared.global [%0], [%1], 16;" :: "r"(dst), "l"(src));
}
__device__ __forceinline__ void cp_commit() { asm volatile("cp.async.commit_group;"); }
__device__ __forceinline__ void cp_wait0() { asm volatile("cp.async.wait_group 0;"); }

// ---------------- block reductions (ln kernel) ----------------
__device__ __forceinline__ float block_sum(float v) {
    __shared__ float sh[33];
    int lane = threadIdx.x & 31, w = threadIdx.x >> 5;
    #pragma unroll
    for (int o = 16; o; o >>= 1) v += __shfl_xor_sync(0xffffffffu, v, o);
    __syncthreads();
    if (lane == 0) sh[w] = v;
    __syncthreads();
    if (w == 0) {
        float x = (lane < 8) ? sh[lane] : 0.0f;
        #pragma unroll
        for (int o = 4; o; o >>= 1) x += __shfl_xor_sync(0xffffffffu, x, o);
        if (lane == 0) sh[32] = x;
    }
    __syncthreads();
    return sh[32];
}

// ---------------- projections / output GEMM (R7 pipeline, x4 B-loads) ----------------
__global__ void __launch_bounds__(256) gemm8192(const float* __restrict__ A0,
                                                const float* __restrict__ A1,
                                                const float* __restrict__ A2,
                                                const float* __restrict__ W0,
                                                const float* __restrict__ W1,
                                                const float* __restrict__ W2,
                                                int modeBase) {
    extern __shared__ char smraw[];
    int mode = modeBase + blockIdx.z;
    const float* Ap = (mode == 0) ? A0 : (mode == 1) ? A1 : (mode == 2) ? A2 : g_ctx;
    const float* W  = (mode == 1) ? W1 : (mode == 2) ? W2 : W0;
    int t = threadIdx.x, lane = t & 31, wid = t >> 5;
    int wm = wid >> 2, wn = wid & 3;
    int m0 = blockIdx.y * 128, n0 = blockIdx.x * 128;
    int ar = t >> 4, ac4 = (t & 15) * 4;
    int bk = t >> 5, bc4 = (t & 31) * 4;
    uint32_t sBase = smaddr(smraw);

    float4 pa[8], pb[8];
    float acc[4][4][4];
    #pragma unroll
    for (int i = 0; i < 4; i++)
        #pragma unroll
        for (int j = 0; j < 4; j++)
            #pragma unroll
            for (int e = 0; e < 4; e++) acc[i][j][e] = 0.0f;

    #pragma unroll
    for (int p = 0; p < 8; p++) {
        pa[p] = *(const float4*)&Ap[(size_t)(m0 + ar + 16 * p) * 1024 + ac4];
        pb[p] = *(const float4*)&W[(size_t)(bk + 8 * p) * 1024 + n0 + bc4];
    }

    for (int kt = 0; kt < 16; kt++) {
        int buf = kt & 1;
        char* Ah = smraw + buf * 65536;
        char* Al = Ah + 16384;
        char* Bh = Al + 16384;
        char* Bl = Bh + 16384;
        #pragma unroll
        for (int p = 0; p < 8; p++) {
            uint2 h, l;
            split4(pa[p], h, l);
            uint32_t off = SW128((ar + 16 * p) * 128 + ac4 * 2);
            *(uint2*)(Ah + off) = h; *(uint2*)(Al + off) = l;
            split4(pb[p], h, l);
            uint32_t offb = SW256((bk + 8 * p) * 256 + bc4 * 2);
            *(uint2*)(Bh + offb) = h; *(uint2*)(Bl + offb) = l;
        }
        __syncthreads();
        if (kt < 15) {
            #pragma unroll
            for (int p = 0; p < 8; p++) {
                pa[p] = *(const float4*)&Ap[(size_t)(m0 + ar + 16 * p) * 1024 + (kt + 1) * 64 + ac4];
                pb[p] = *(const float4*)&W[(size_t)((kt + 1) * 64 + bk + 8 * p) * 1024 + n0 + bc4];
            }
        }
        uint32_t sAh = sBase + buf * 65536, sAl = sAh + 16384;
        uint32_t sBh = sAl + 16384, sBl = sBh + 16384;
        #pragma unroll
        for (int ks = 0; ks < 4; ks++) {
            uint32_t bhf[4][2], blf[4][2];
            #pragma unroll
            for (int in2 = 0; in2 < 4; in2 += 2) {
                int krow = ks * 16 + (lane & 15);
                int nb = (wn * 32 + (in2 + (lane >> 4)) * 8) * 2;
                uint32_t off = SW256(krow * 256 + nb);
                ldsm4t(bhf[in2][0], bhf[in2][1], bhf[in2 + 1][0], bhf[in2 + 1][1], sBh + off);
                ldsm4t(blf[in2][0], blf[in2][1], blf[in2 + 1][0], blf[in2 + 1][1], sBl + off);
            }
            #pragma unroll
            for (int im = 0; im < 4; im++) {
                int arow = wm * 64 + im * 16 + (lane & 15);
                int acb = (ks * 16 + ((lane >> 4) << 3)) * 2;
                uint32_t off = SW128(arow * 128 + acb);
                uint32_t ah[4], al[4];
                ldsm4(ah[0], ah[1], ah[2], ah[3], sAh + off);
                ldsm4(al[0], al[1], al[2], al[3], sAl + off);
                #pragma unroll
                for (int in = 0; in < 4; in++) {
                    mmab(acc[im][in], ah, bhf[in]);
                    mmab(acc[im][in], al, bhf[in]);
                    mmab(acc[im][in], ah, blf[in]);
                }
            }
        }
    }

    int g = lane >> 2, c2 = (lane & 3) * 2;
    #pragma unroll
    for (int im = 0; im < 4; im++)
        #pragma unroll
        for (int in = 0; in < 4; in++)
            #pragma unroll
            for (int hh = 0; hh < 2; hh++) {
                int m = m0 + wm * 64 + im * 16 + g + hh * 8;
                int n = n0 + wn * 32 + in * 8 + c2;
                float2 v = make_float2(acc[im][in][hh * 2], acc[im][in][hh * 2 + 1]);
                if (mode <= 2) {
                    __nv_bfloat16* Oh = (mode == 0) ? g_Qh : (mode == 1) ? g_Kh : g_Vh;
                    __nv_bfloat16* Ol = (mode == 0) ? g_Ql : (mode == 1) ? g_Kl : g_Vl;
                    int b = m >> 11, s = m & 2047;
                    int h = n >> 6, d = n & 63;
                    size_t idx = ((size_t)(b * Hq + h) * Sq + s) * 64 + d;
                    uint32_t hb, lb; pk2bf(v.x, v.y, hb, lb);
                    *(uint32_t*)&Oh[idx] = hb;
                    *(uint32_t*)&Ol[idx] = lb;
                } else {
                    *(float2*)&g_proj[(size_t)m * 1024 + n] = v;
                }
            }
}

// ---------------- pass A: stats-only scores (x4 K loads) ----------------
__global__ void __launch_bounds__(256, 2) scores_stats(const unsigned char* __restrict__ mask) {
    extern __shared__ char smraw[];
    char* Qh = smraw;
    char* Ql = Qh + 16384;
    char* Kh = Ql + 16384;
    char* Kl = Kh + 16384;
    int t = threadIdx.x, lane = t & 31, wid = t >> 5;
    int wm = wid >> 2, wn = wid & 3;
    int bh = blockIdx.z, q0 = blockIdx.y * 128, k0 = blockIdx.x * 128;
    size_t base = (size_t)bh * Sq * 64;
    uint32_t sQh = smaddr(Qh), sQl = smaddr(Ql), sKh = smaddr(Kh), sKl = smaddr(Kl);

    #pragma unroll
    for (int p = 0; p < 8; p++) {
        int r = (t >> 4) + 16 * p, c4 = (t & 15) * 4;
        uint32_t off = SW128(r * 128 + c4 * 2);
        size_t qi = base + (size_t)(q0 + r) * 64 + c4;
        size_t ki = base + (size_t)(k0 + r) * 64 + c4;
        *(uint2*)(Qh + off) = *(const uint2*)&g_Qh[qi];
        *(uint2*)(Ql + off) = *(const uint2*)&g_Ql[qi];
        *(uint2*)(Kh + off) = *(const uint2*)&g_Kh[ki];
        *(uint2*)(Kl + off) = *(const uint2*)&g_Kl[ki];
    }
    __syncthreads();

    float acc[4][4][4];
    #pragma unroll
    for (int i = 0; i < 4; i++)
        #pragma unroll
        for (int j = 0; j < 4; j++)
            #pragma unroll
            for (int e = 0; e < 4; e++) acc[i][j][e] = 0.0f;

    #pragma unroll
    for (int ks = 0; ks < 4; ks++) {
        uint32_t bhf[4][2], blf[4][2];
        #pragma unroll
        for (int in2 = 0; in2 < 4; in2 += 2) {
            int nrow = wn * 32 + (in2 + (lane >> 4)) * 8 + (lane & 7);
            int cb = (ks * 16 + (lane & 8)) * 2;
            uint32_t off = SW128(nrow * 128 + cb);
            ldsm4(bhf[in2][0], bhf[in2][1], bhf[in2 + 1][0], bhf[in2 + 1][1], sKh + off);
            ldsm4(blf[in2][0], blf[in2][1], blf[in2 + 1][0], blf[in2 + 1][1], sKl + off);
        }
        #pragma unroll
        for (int im = 0; im < 4; im++) {
            int arow = wm * 64 + im * 16 + (lane & 15);
            int acb = (ks * 16 + ((lane >> 4) << 3)) * 2;
            uint32_t off = SW128(arow * 128 + acb);
            uint32_t ah[4], al[4];
            ldsm4(ah[0], ah[1], ah[2], ah[3], sQh + off);
            ldsm4(al[0], al[1], al[2], al[3], sQl + off);
            #pragma unroll
            for (int in = 0; in < 4; in++) {
                mmab(acc[im][in], ah, bhf[in]);
                mmab(acc[im][in], al, bhf[in]);
                mmab(acc[im][in], ah, blf[in]);
            }
        }
    }

    int b = bh >> 4;
    int g = lane >> 2, c2 = (lane & 3) * 2;
    #pragma unroll
    for (int im = 0; im < 4; im++)
        #pragma unroll
        for (int hh = 0; hh < 2; hh++) {
            int q = q0 + wm * 64 + im * 16 + g + hh * 8;
            float vals[8];
            #pragma unroll
            for (int in = 0; in < 4; in++) {
                int kc = k0 + wn * 32 + in * 8 + c2;
                unsigned short mk = *(const unsigned short*)&mask[(size_t)b * Sq * Sq + (size_t)q * Sq + kc];
                vals[in * 2]     = (mk & 0xffu) ? -1e9f : acc[im][in][hh * 2] * 0.125f;
                vals[in * 2 + 1] = ((mk >> 8) & 0xffu) ? -1e9f : acc[im][in][hh * 2 + 1] * 0.125f;
            }
            float m = vals[0];
            #pragma unroll
            for (int i = 1; i < 8; i++) m = fmaxf(m, vals[i]);
            m = fmaxf(m, __shfl_xor_sync(0xffffffffu, m, 1));
            m = fmaxf(m, __shfl_xor_sync(0xffffffffu, m, 2));
            float s = 0.0f;
            #pragma unroll
            for (int i = 0; i < 8; i++) s += __expf(vals[i] - m);
            s += __shfl_xor_sync(0xffffffffu, s, 1);
            s += __shfl_xor_sync(0xffffffffu, s, 2);
            if ((lane & 3) == 0)
                g_pstat[((size_t)bh * Sq + q) * 64 + blockIdx.x * 4 + wn] = make_float2(m, s);
        }
}

// ---------------- fold 64 partials per row -> rowmax, rinv ----------------
__global__ void __launch_bounds__(256) reduce_stats() {
    int r = blockIdx.x * 8 + (threadIdx.x >> 5);
    int lane = threadIdx.x & 31;
    float2 a = g_pstat[(size_t)r * 64 + lane];
    float2 b = g_pstat[(size_t)r * 64 + 32 + lane];
    float m = fmaxf(a.x, b.x);
    #pragma unroll
    for (int o = 16; o; o >>= 1) m = fmaxf(m, __shfl_xor_sync(0xffffffffu, m, o));
    float s = a.y * __expf(a.x - m) + b.y * __expf(b.x - m);
    #pragma unroll
    for (int o = 16; o; o >>= 1) s += __shfl_xor_sync(0xffffffffu, s, o);
    if (lane == 0) { g_rowmax[r] = m; g_rinv[r] = 1.0f / s; }
}

// ---------------- pass B: recompute QK^T, write probs, P@V ----------------
// V uses hi plane only (P·bf16(V)); K x4 loads; V x4.trans loads.
// smem: Qh 16K | Ql 16K | 2 stages x {Kh 8K | Kl 8K | Vh 8K} = 80KB
__global__ void __launch_bounds__(256, 2) fused_pv(const unsigned char* __restrict__ mask,
                                                   float* __restrict__ attn) {
    extern __shared__ char smraw[];
    int t = threadIdx.x, lane = t & 31, w = t >> 5;
    int g = lane >> 2, c2 = (lane & 3) * 2;
    int bh = blockIdx.y, q0 = blockIdx.x * 128;
    size_t base = (size_t)bh * Sq * 64;
    uint32_t sBase = smaddr(smraw);
    uint32_t sQh = sBase, sQl = sBase + 16384;

    // Q tile staging (one-time)
    {
        int qr = t >> 1, qc = (t & 1) * 32;
        #pragma unroll
        for (int p = 0; p < 4; p++) {
            size_t qi = base + (size_t)(q0 + qr) * 64 + qc + p * 8;
            uint32_t off = SW128(qr * 128 + (qc + p * 8) * 2);
            *(uint4*)(smraw + off) = *(const uint4*)&g_Qh[qi];
            *(uint4*)(smraw + 16384 + off) = *(const uint4*)&g_Ql[qi];
        }
    }

    // K/V staging: 64 rows x 128B per plane; 4 thr/row, 2 x 16B chunks each
    int kr = t >> 2, kc = (t & 3) * 16;
    uint32_t soff0 = SW128(kr * 128 + kc * 2);
    uint32_t soff1 = SW128(kr * 128 + kc * 2 + 16);
    {
        uint32_t s0 = sBase + 32768;
        size_t gi = base + (size_t)kr * 64 + kc;
        cpasync16(s0 + soff0,         &g_Kh[gi]);     cpasync16(s0 + soff1,         &g_Kh[gi + 8]);
        cpasync16(s0 + 8192 + soff0,  &g_Kl[gi]);     cpasync16(s0 + 8192 + soff1,  &g_Kl[gi + 8]);
        cpasync16(s0 + 16384 + soff0, &g_Vh[gi]);     cpasync16(s0 + 16384 + soff1, &g_Vh[gi + 8]);
        cp_commit();
    }

    int qa = q0 + w * 16 + g, qb = qa + 8;
    float mxa = g_rowmax[bh * Sq + qa], ria = g_rinv[bh * Sq + qa];
    float mxb = g_rowmax[bh * Sq + qb], rib = g_rinv[bh * Sq + qb];
    size_t rowa = (size_t)bh * Sq * Sq + (size_t)qa * Sq;
    size_t rowb = (size_t)bh * Sq * Sq + (size_t)qb * Sq;
    const unsigned char* mrowa = mask + (size_t)(bh >> 4) * Sq * Sq + (size_t)qa * Sq;
    const unsigned char* mrowb = mask + (size_t)(bh >> 4) * Sq * Sq + (size_t)qb * Sq;

    float accc[8][4];
    #pragma unroll
    for (int j = 0; j < 8; j++)
        #pragma unroll
        for (int e = 0; e < 4; e++) accc[j][e] = 0.0f;

    for (int kt = 0; kt < 32; kt++) {
        int buf = kt & 1;
        cp_wait0();
        __syncthreads();
        if (kt < 31) {
            uint32_t sn = sBase + 32768 + (buf ^ 1) * 24576;
            size_t gi = base + (size_t)((kt + 1) * 64 + kr) * 64 + kc;
            cpasync16(sn + soff0,         &g_Kh[gi]);     cpasync16(sn + soff1,         &g_Kh[gi + 8]);
            cpasync16(sn + 8192 + soff0,  &g_Kl[gi]);     cpasync16(sn + 8192 + soff1,  &g_Kl[gi + 8]);
            cpasync16(sn + 16384 + soff0, &g_Vh[gi]);     cpasync16(sn + 16384 + soff1, &g_Vh[gi + 8]);
            cp_commit();
        }
        uint32_t sKh = sBase + 32768 + buf * 24576, sKl = sKh + 8192, sVh = sKh + 16384;

        // ---- S = Q K^T (3-term) ----
        float accs[8][4];
        #pragma unroll
        for (int j = 0; j < 8; j++)
            #pragma unroll
            for (int e = 0; e < 4; e++) accs[j][e] = 0.0f;
        #pragma unroll
        for (int ks = 0; ks < 4; ks++) {
            int arow = w * 16 + (lane & 15);
            int acb = (ks * 16 + ((lane >> 4) << 3)) * 2;
            uint32_t offa = SW128(arow * 128 + acb);
            uint32_t ah[4], al[4];
            ldsm4(ah[0], ah[1], ah[2], ah[3], sQh + offa);
            ldsm4(al[0], al[1], al[2], al[3], sQl + offa);
            #pragma unroll
            for (int in2 = 0; in2 < 8; in2 += 2) {
                int nrow = (in2 + (lane >> 4)) * 8 + (lane & 7);
                int cb = (ks * 16 + (lane & 8)) * 2;
                uint32_t off = SW128(nrow * 128 + cb);
                uint32_t k0r, k1r, k2r, k3r, l0r, l1r, l2r, l3r;
                ldsm4(k0r, k1r, k2r, k3r, sKh + off);
                ldsm4(l0r, l1r, l2r, l3r, sKl + off);
                uint32_t bh0[2] = {k0r, k1r}, bh1[2] = {k2r, k3r};
                uint32_t bl0[2] = {l0r, l1r}, bl1[2] = {l2r, l3r};
                mmab(accs[in2], ah, bh0); mmab(accs[in2], al, bh0); mmab(accs[in2], ah, bl0);
                mmab(accs[in2 + 1], ah, bh1); mmab(accs[in2 + 1], al, bh1); mmab(accs[in2 + 1], ah, bl1);
            }
        }

        // ---- epilogue + PV (2-term: P * bf16(V)) ----
        #pragma unroll
        for (int ks = 0; ks < 4; ks++) {
            uint32_t ahp[4], alp[4];
            #pragma unroll
            for (int half = 0; half < 2; half++) {
                int in = 2 * ks + half;
                int kcol = kt * 64 + in * 8 + c2;
                unsigned short mka = *(const unsigned short*)&mrowa[kcol];
                unsigned short mkb = *(const unsigned short*)&mrowb[kcol];
                float fa0 = (mka & 0xffu) ? -1e9f : accs[in][0] * 0.125f;
                float fa1 = ((mka >> 8) & 0xffu) ? -1e9f : accs[in][1] * 0.125f;
                float fb0 = (mkb & 0xffu) ? -1e9f : accs[in][2] * 0.125f;
                float fb1 = ((mkb >> 8) & 0xffu) ? -1e9f : accs[in][3] * 0.125f;
                float pa0 = __expf(fa0 - mxa) * ria;
                float pa1 = __expf(fa1 - mxa) * ria;
                float pb0 = __expf(fb0 - mxb) * rib;
                float pb1 = __expf(fb1 - mxb) * rib;
                *(float2*)&attn[rowa + kcol] = make_float2(pa0, pa1);
                *(float2*)&attn[rowb + kcol] = make_float2(pb0, pb1);
                pk2bf(pa0, pa1, ahp[half * 2], alp[half * 2]);
                pk2bf(pb0, pb1, ahp[half * 2 + 1], alp[half * 2 + 1]);
            }
            #pragma unroll
            for (int jn2 = 0; jn2 < 8; jn2 += 2) {
                int krow = ks * 16 + (lane & 15);
                int col = (jn2 + (lane >> 4)) * 16;
                uint32_t off = SW128(krow * 128 + col);
                uint32_t v0, v1, v2, v3;
                ldsm4t(v0, v1, v2, v3, sVh + off);
                uint32_t bv0[2] = {v0, v1}, bv1[2] = {v2, v3};
                mmab(accc[jn2], ahp, bv0); mmab(accc[jn2], alp, bv0);
                mmab(accc[jn2 + 1], ahp, bv1); mmab(accc[jn2 + 1], alp, bv1);
            }
        }
    }

    int b = bh >> 4, h = bh & 15;
    #pragma unroll
    for (int jn = 0; jn < 8; jn++)
        #pragma unroll
        for (int hh = 0; hh < 2; hh++) {
            int q = q0 + w * 16 + g + hh * 8;
            int n = jn * 8 + c2;
            float2 v = make_float2(accc[jn][hh * 2], accc[jn][hh * 2 + 1]);
            *(float2*)&g_ctx[(size_t)(b * Sq + q) * 1024 + h * 64 + n] = v;
        }
}

// ---------------- residual + LayerNorm ----------------
__global__ void __launch_bounds__(256) ln_kernel(const float* __restrict__ inQ,
                                                 const float* __restrict__ gamma,
                                                 const float* __restrict__ beta,
                                                 float* __restrict__ out) {
    int m = blockIdx.x, t = threadIdx.x;
    size_t base = (size_t)m * 1024;
    float x[4];
    float s = 0.0f;
    #pragma unroll
    for (int i = 0; i < 4; i++) {
        int c = i * 256 + t;
        x[i] = g_proj[base + c] + inQ[base + c];
        s += x[i];
    }
    s = block_sum(s);
    float mu = s * (1.0f / 1024.0f);
    float s2 = 0.0f;
    #pragma unroll
    for (int i = 0; i < 4; i++) { float d = x[i] - mu; s2 += d * d; }
    s2 = block_sum(s2);
    float rstd = rsqrtf(s2 * (1.0f / 1024.0f) + 1e-5f);
    #pragma unroll
    for (int i = 0; i < 4; i++) {
        int c = i * 256 + t;
        out[base + c] = (x[i] - mu) * rstd * gamma[c] + beta[c];
    }
}

// ---------------- launch ----------------
extern "C" void kernel_launch(void* const* d_in, const int* in_sizes, int n_in,
                              void* d_out, int out_size) {
    const float* inQ = (const float*)d_in[0];
    const float* inK = (const float*)d_in[1];
    const float* inV = (const float*)d_in[2];
    const unsigned char* mask = (const unsigned char*)d_in[3];
    const float* wQ = (const float*)d_in[4];
    const float* wK = (const float*)d_in[5];
    const float* wV = (const float*)d_in[6];
    const float* wO = (const float*)d_in[7];
    const float* gamma = (const float*)d_in[8];
    const float* beta = (const float*)d_in[9];
    float* out = (float*)d_out;
    float* attn = out + (size_t)Bq * Sq * Eq;

    const int GEMM_SMEM = 131072;
    const int SC_SMEM   = 65536;
    const int FP_SMEM   = 81920;   // Q 32KB + 2 x 24KB KV stages
    cudaFuncSetAttribute(gemm8192, cudaFuncAttributeMaxDynamicSharedMemorySize, GEMM_SMEM);
    cudaFuncSetAttribute(scores_stats, cudaFuncAttributeMaxDynamicSharedMemorySize, SC_SMEM);
    cudaFuncSetAttribute(fused_pv, cudaFuncAttributeMaxDynamicSharedMemorySize, FP_SMEM);

    gemm8192<<<dim3(8, 64, 3), 256, GEMM_SMEM>>>(inQ, inK, inV, wQ, wK, wV, 0);
    scores_stats<<<dim3(16, 16, 64), 256, SC_SMEM>>>(mask);
    reduce_stats<<<Bq * Hq * Sq / 8, 256>>>();
    fused_pv<<<dim3(16, 64), 256, FP_SMEM>>>(mask, attn);
    gemm8192<<<dim3(8, 64, 1), 256, GEMM_SMEM>>>(nullptr, nullptr, nullptr, wO, nullptr, nullptr, 3);
    ln_kernel<<<Bq * Sq, 256>>>(inQ, gamma, beta, out);
}